// round 15
// baseline (speedup 1.0000x reference)
#include <cuda_runtime.h>
#include <cuda_fp16.h>
#include <math.h>
#include <stdint.h>

#define BV 8
#define SLEN 1024
#define DD 128
#define EE 4
#define ED 512
#define MM (BV*SLEN)          // 8192 rows
#define KGR (SLEN*EE)         // 4096 graph K
#define NSTEPS 5
#define KB2 64                // K elems per pipeline stage (128B rows)

typedef __half fp16;

// smem per stage: (MTILE + NB) rows x 144 B
#define SM_GR (3*(128+128)*144)   // graph: M128/N128, 3 stages = 110592
#define SM_GF (2*(128+128)*144)   // gfull: M128/N128, 2 stages = 73728
#define SM_RZ (2*(64+128)*144)    // rz: M64/N128, 2 stages = 55296
#define SM_UP (2*(32+128)*144)    // update: M32/N128, 2 stages = 46080

// ---------------- device scratch (no allocation allowed) ----------------
__device__ fp16 g_WeffH[2][ED*DD];        // folded W_in/W_out, ROW-PERMUTED n'=d*4+e
__device__ float g_biasP[2][ED];          // permuted b_in/b_out
__device__ fp16 g_WrzH[256*384];          // stacked [W_r; W_z] fp16
__device__ fp16 g_WtH[128*384];           // W_t fp16
__device__ float g_brz[256];
__device__ fp16 g_gh[(size_t)2*MM*KGR];       // fp16 gin/gout (134MB)
__device__ fp16 g_gfullT[(size_t)2*BV*DD*KGR];// [t][b][d=128][k=4096] fp16 K-major
__device__ fp16 g_gpartH[(size_t)2*2*MM*DD];  // split-K partials fp16 [ks][t][m][d]
__device__ fp16 g_gsumH[2][MM*DD];        // gi / go fp16 (GEMM A operand)
__device__ int  g_flags[128];             // split-K arrival flags (one per (m,b,t) tile)
__device__ fp16 g_rgH[MM*DD];             // r * out, fp16
__device__ fp16 g_stateH[MM*DD];          // fp16 shadow of state
__device__ float g_z[MM*DD];              // z (fp32, blend)
__device__ float g_stateA[MM*DD];
__device__ float g_stateB[MM*DD];

__device__ __forceinline__ const float* state_ptr(const float* ext, int sel) {
    return sel == 0 ? g_stateA : (sel == 1 ? g_stateB : ext);
}

__device__ __forceinline__ void mma_f16(float* d, const uint32_t* a, const uint32_t* b) {
    asm volatile(
        "mma.sync.aligned.m16n8k16.row.col.f32.f16.f16.f32 "
        "{%0,%1,%2,%3}, {%4,%5,%6,%7}, {%8,%9}, {%0,%1,%2,%3};"
        : "+f"(d[0]), "+f"(d[1]), "+f"(d[2]), "+f"(d[3])
        : "r"(a[0]), "r"(a[1]), "r"(a[2]), "r"(a[3]), "r"(b[0]), "r"(b[1]));
}
__device__ __forceinline__ void ldm_x4(uint32_t* r, uint32_t addr) {
    asm volatile("ldmatrix.sync.aligned.m8n8.x4.shared.b16 {%0,%1,%2,%3}, [%4];"
                 : "=r"(r[0]), "=r"(r[1]), "=r"(r[2]), "=r"(r[3]) : "r"(addr));
}
__device__ __forceinline__ void cp16(uint32_t smem_dst, const void* gsrc) {
    asm volatile("cp.async.cg.shared.global [%0], [%1], 16;" :: "r"(smem_dst), "l"(gsrc));
}
#define CP_COMMIT() asm volatile("cp.async.commit_group;" ::: "memory")

// ---------------- unified fp16 GEMM core ----------------
template<int KTOT, int LDA, int LDB, int NSTG, int MTILE, int NB, int NFRAG, int MF>
__device__ __forceinline__ void h_core(
    const fp16* __restrict__ A0, const fp16* __restrict__ A1, const fp16* __restrict__ A2,
    const fp16* __restrict__ Bt, int m0, int n0, float (&acc)[MF][NFRAG][4], char* dsm)
{
    constexpr int ATILE_B = MTILE*144;
    constexpr int STGB = ATILE_B + NB*144;
    constexpr int NITL = KTOT / KB2;
    constexpr int WMc = (MTILE == 128) ? 2 : 1;
    static_assert(MF == MTILE/(WMc*16), "MF mismatch");
    const uint32_t sb = (uint32_t)__cvta_generic_to_shared(dsm);
    const int tid = threadIdx.x, lane = tid & 31, wid = tid >> 5;
    const int l8 = lane & 7, q = lane >> 3;
    const int wm = (WMc == 2) ? (wid & 1) : 0;
    const int wn = (WMc == 2) ? (wid >> 1) : wid;

    auto issue = [&](int stg, int k0) {
        if (k0 < KTOT) {
            const fp16* Aseg; int kl;
            if (KTOT > LDA) {              // 3 x 128-wide segments
                Aseg = (k0 < 128) ? A0 : (k0 < 256 ? A1 : A2);
                kl = k0 & 127;
            } else { Aseg = A0; kl = k0; }
            uint32_t base = sb + stg*STGB;
            #pragma unroll
            for (int i = 0; i < MTILE*8/256; i++) {
                int c = tid + i*256, row = c >> 3, off = c & 7;
                cp16(base + row*144 + off*16,
                     Aseg + (size_t)(m0+row)*LDA + kl + off*8);
            }
            #pragma unroll
            for (int i = 0; i < NB*8/256; i++) {
                int c = tid + i*256, row = c >> 3, off = c & 7;
                cp16(base + ATILE_B + row*144 + off*16,
                     Bt + (size_t)(n0+row)*LDB + k0 + off*8);
            }
        }
        CP_COMMIT();
    };

    #pragma unroll
    for (int s = 0; s < NSTG-1; s++) issue(s, s*KB2);

    #pragma unroll 1
    for (int it = 0; it < NITL; ++it) {
        asm volatile("cp.async.wait_group %0;" :: "n"(NSTG-2) : "memory");
        __syncthreads();
        issue((it + NSTG-1) % NSTG, (it + NSTG-1)*KB2);

        const uint32_t sA = sb + (it % NSTG)*STGB;
        const uint32_t sB = sA + ATILE_B;
        #pragma unroll
        for (int kk = 0; kk < 4; kk++) {
            uint32_t afr[MF][4], bfr[NFRAG][2];
            #pragma unroll
            for (int mf = 0; mf < MF; mf++) {
                int row = wm*64 + mf*16 + (q & 1)*8 + l8;
                ldm_x4(afr[mf], sA + row*144 + kk*32 + (q >> 1)*16);
            }
            #pragma unroll
            for (int h = 0; h < NFRAG/2; h++) {
                uint32_t r[4];
                int row = wn*(8*NFRAG) + h*16 + (q >> 1)*8 + l8;
                ldm_x4(r, sB + row*144 + kk*32 + (q & 1)*16);
                bfr[2*h][0] = r[0]; bfr[2*h][1] = r[1];
                bfr[2*h+1][0] = r[2]; bfr[2*h+1][1] = r[3];
            }
            #pragma unroll
            for (int mf = 0; mf < MF; mf++)
                #pragma unroll
                for (int nf = 0; nf < NFRAG; nf++)
                    mma_f16(acc[mf][nf], afr[mf], bfr[nf]);
        }
    }
}

// ---------------- merged prep kernel (fold + stack + cvtX) ----------------
__global__ void k_prep(const float* __restrict__ Win, const float* __restrict__ Wout,
                       const float* __restrict__ b_in, const float* __restrict__ b_out,
                       const float* __restrict__ Wr, const float* __restrict__ Wz,
                       const float* __restrict__ br, const float* __restrict__ bz,
                       const float* __restrict__ Wt, const float* __restrict__ x)
{
    int b = blockIdx.x, tid = threadIdx.x;
    if (b < 512) {
        int idx = b*256 + tid;
        int t = idx >> 16, rem = idx & 65535, j = rem >> 7, d = rem & 127;
        const float* W = t ? Wout : Win;
        float s = 0.f;
        #pragma unroll
        for (int e = 0; e < EE; e++) s += W[(size_t)j*ED + e*DD + d];
        int np = (j & 127)*4 + (j >> 7);
        g_WeffH[t][np*DD + d] = __float2half_rn(s);
        if (d == 0) g_biasP[t][np] = (t ? b_out : b_in)[j];
    } else if (b < 896) {
        int i = (b - 512)*256 + tid;
        if (i < 256*384) {
            int row = i / 384, col = i % 384;
            g_WrzH[i] = __float2half_rn((row < 128) ? Wr[row*384 + col]
                                                    : Wz[(row-128)*384 + col]);
        }
        if (i < 128*384) g_WtH[i] = __float2half_rn(Wt[i]);
        if (i < 256) g_brz[i] = (i < 128) ? br[i] : bz[i-128];
    } else {
        size_t i = ((size_t)(b - 896)*256 + tid) * 4;
        float4 f = *(const float4*)(x + i);
        fp16 h[4];
        h[0]=__float2half_rn(f.x); h[1]=__float2half_rn(f.y);
        h[2]=__float2half_rn(f.z); h[3]=__float2half_rn(f.w);
        *(uint2*)(g_stateH + i) = *(uint2*)h;
    }
}

__global__ void k_cvtA(const float* __restrict__ gin, const float* __restrict__ gout) {
    int t = blockIdx.y;
    const float* src = t ? gout : gin;
    fp16* dst = g_gh + (size_t)t*MM*KGR;
    size_t i = ((size_t)blockIdx.x*blockDim.x + threadIdx.x) * 8;
    float4 f0 = *(const float4*)(src + i);
    float4 f1 = *(const float4*)(src + i + 4);
    fp16 h[8];
    h[0]=__float2half_rn(f0.x); h[1]=__float2half_rn(f0.y);
    h[2]=__float2half_rn(f0.z); h[3]=__float2half_rn(f0.w);
    h[4]=__float2half_rn(f1.x); h[5]=__float2half_rn(f1.y);
    h[6]=__float2half_rn(f1.z); h[7]=__float2half_rn(f1.w);
    *(uint4*)(dst + i) = *(uint4*)h;
}

// ---------------- K1: gfullT = (XH @ WeffH'^T + b') -> fp16 transposed, coalesced ----------------
// Also zeroes the split-K arrival flags for this step (runs before k_graph_h).
__global__ __launch_bounds__(256, 2) void k_gfull_h(int dummy)
{
    extern __shared__ char dsm[];
    if (blockIdx.x == 0 && blockIdx.y == 0 && blockIdx.z == 0 && threadIdx.x < 128)
        g_flags[threadIdx.x] = 0;

    const int t = blockIdx.z;
    const int m0 = blockIdx.y*128, n0 = blockIdx.x*128;
    float acc[4][4][4] = {};
    h_core<128,128,128,2,128,128,4,4>(g_stateH, g_stateH, g_stateH, g_WeffH[t], m0, n0, acc, dsm);

    const float* bias = g_biasP[t];
    const int lane = threadIdx.x & 31, wid = threadIdx.x >> 5;
    const int g = lane >> 2, tig = lane & 3;
    const int wm = wid & 1, wn = wid >> 1;
    const int bb = m0 >> 10;
    fp16* outT = g_gfullT + ((size_t)t*BV + bb)*DD*KGR;
    #pragma unroll
    for (int mf = 0; mf < 4; mf++) {
        int m = m0 + wm*64 + mf*16 + g;
        int s0 = m & (SLEN-1), s1 = (m+8) & (SLEN-1);
        #pragma unroll
        for (int nf = 0; nf < 4; nf++) {
            int np = n0 + wn*32 + nf*8 + 2*tig;        // n' = d*4+e, even
            int d = np >> 2, e = np & 3;
            fp16 p0[2] = {__float2half_rn(acc[mf][nf][0] + bias[np]),
                          __float2half_rn(acc[mf][nf][1] + bias[np+1])};
            fp16 p1[2] = {__float2half_rn(acc[mf][nf][2] + bias[np]),
                          __float2half_rn(acc[mf][nf][3] + bias[np+1])};
            *(uint32_t*)(outT + (size_t)d*KGR + s0*4 + e) = *(uint32_t*)p0;
            *(uint32_t*)(outT + (size_t)d*KGR + s1*4 + e) = *(uint32_t*)p1;
        }
    }
}

// ---------------- K2: graph GEMM, split-K(2) with fused last-CTA reduction ----------------
__global__ __launch_bounds__(256, 2) void k_graph_h(int dummy)
{
    extern __shared__ char dsm[];
    const int bt = blockIdx.y, t = bt & 1, b = bt >> 1;
    const int ks = blockIdx.z;
    const int m0 = blockIdx.x * 128;
    const fp16* A  = g_gh + (size_t)t*MM*KGR + (size_t)b*SLEN*KGR + ks*(KGR/2);
    const fp16* Bg = g_gfullT + ((size_t)t*BV + b)*DD*KGR + ks*(KGR/2);
    fp16* P = g_gpartH + (((size_t)ks*2 + t)*MM + (size_t)b*SLEN)*DD;

    float acc[4][4][4] = {};
    h_core<KGR/2, KGR, KGR, 3, 128, 128, 4, 4>(A, A, A, Bg, m0, 0, acc, dsm);

    const int lane = threadIdx.x & 31, wid = threadIdx.x >> 5;
    const int g = lane >> 2, tig = lane & 3;
    const int wm = wid & 1, wn = wid >> 1;

    // 1) publish own partial (fp16)
    #pragma unroll
    for (int mf = 0; mf < 4; mf++) {
        int m = m0 + wm*64 + mf*16 + g;
        #pragma unroll
        for (int nf = 0; nf < 4; nf++) {
            int n = wn*32 + nf*8 + 2*tig;
            fp16 p0[2] = {__float2half_rn(acc[mf][nf][0]), __float2half_rn(acc[mf][nf][1])};
            fp16 p1[2] = {__float2half_rn(acc[mf][nf][2]), __float2half_rn(acc[mf][nf][3])};
            *(uint32_t*)(P + (size_t)m*DD + n)     = *(uint32_t*)p0;
            *(uint32_t*)(P + (size_t)(m+8)*DD + n) = *(uint32_t*)p1;
        }
    }

    // 2) arrival protocol: second arriver reduces
    __threadfence();
    __syncthreads();
    __shared__ int s_old;
    if (threadIdx.x == 0)
        s_old = atomicAdd(&g_flags[blockIdx.x + 8*blockIdx.y], 1);
    __syncthreads();

    if (s_old == 1) {
        __threadfence();   // acquire peer's stores
        const fp16* Pp = g_gpartH + (((size_t)(ks^1)*2 + t)*MM + (size_t)b*SLEN)*DD;
        fp16* C = g_gsumH[t] + (size_t)b*SLEN*DD;
        #pragma unroll
        for (int mf = 0; mf < 4; mf++) {
            int m = m0 + wm*64 + mf*16 + g;
            #pragma unroll
            for (int nf = 0; nf < 4; nf++) {
                int n = wn*32 + nf*8 + 2*tig;
                uint32_t u0 = *(const uint32_t*)(Pp + (size_t)m*DD + n);
                uint32_t u1 = *(const uint32_t*)(Pp + (size_t)(m+8)*DD + n);
                float2 f0 = __half22float2(*(__half2*)&u0);
                float2 f1 = __half22float2(*(__half2*)&u1);
                fp16 o0[2] = {__float2half_rn(acc[mf][nf][0] + f0.x),
                              __float2half_rn(acc[mf][nf][1] + f0.y)};
                fp16 o1[2] = {__float2half_rn(acc[mf][nf][2] + f1.x),
                              __float2half_rn(acc[mf][nf][3] + f1.y)};
                *(uint32_t*)(C + (size_t)m*DD + n)     = *(uint32_t*)o0;
                *(uint32_t*)(C + (size_t)(m+8)*DD + n) = *(uint32_t*)o1;
            }
        }
    }
}

// ---------------- K3a: r,z = sigmoid([gi,go,X]@[Wr;Wz]^T + b); rgH = fp16(r*X). M64/N128 ----------------
__global__ __launch_bounds__(256, 2) void k_rz_h(const float* __restrict__ Xext, int xsel)
{
    extern __shared__ char dsm[];
    const float* X = state_ptr(Xext, xsel);
    const int m0 = blockIdx.y*64, n0 = blockIdx.x*128;   // n0 in {0,128}
    float acc[4][2][4] = {};
    h_core<384,128,384,2,64,128,2,4>(g_gsumH[0], g_gsumH[1], g_stateH,
                                     g_WrzH + (size_t)n0*384, m0, 0, acc, dsm);

    const int lane = threadIdx.x & 31, wid = threadIdx.x >> 5;
    const int g = lane >> 2, tig = lane & 3;
    #pragma unroll
    for (int mf = 0; mf < 4; mf++) {
        int m = m0 + mf*16 + g;
        #pragma unroll
        for (int nf = 0; nf < 2; nf++) {
            int n = n0 + wid*16 + nf*8 + 2*tig;
            #pragma unroll
            for (int v = 0; v < 4; v++) {
                int mm = (v < 2) ? m : m + 8;
                int nn = n + (v & 1);
                float s = 1.f/(1.f + expf(-(acc[mf][nf][v] + g_brz[nn])));
                if (n0 == 0)
                    g_rgH[(size_t)mm*DD + nn] =
                        __float2half_rn(s * X[(size_t)mm*DD + nn]);
                else
                    g_z[(size_t)mm*DD + (nn - 128)] = s;
            }
        }
    }
}

// ---------------- K3b: h = tanh([gi,go,rg]@Wt^T + bt); out = (1-z)*X + z*h. M32/N128 ----------------
__global__ __launch_bounds__(256, 2) void k_update_h(
    const float* __restrict__ Xext, int xsel,
    const float* __restrict__ bt,
    float* __restrict__ extOut, int osel)
{
    extern __shared__ char dsm[];
    const float* X = state_ptr(Xext, xsel);
    float* out = (osel == 0) ? g_stateA : (osel == 1 ? g_stateB : extOut);
    const int m0 = blockIdx.x*32;
    float acc[2][2][4] = {};
    h_core<384,128,384,2,32,128,2,2>(g_gsumH[0], g_gsumH[1], g_rgH, g_WtH, m0, 0, acc, dsm);

    const int lane = threadIdx.x & 31, wid = threadIdx.x >> 5;
    const int g = lane >> 2, tig = lane & 3;
    #pragma unroll
    for (int mf = 0; mf < 2; mf++) {
        int m = m0 + mf*16 + g;
        #pragma unroll
        for (int nf = 0; nf < 2; nf++) {
            int n = wid*16 + nf*8 + 2*tig;
            #pragma unroll
            for (int v = 0; v < 4; v++) {
                int mm = (v < 2) ? m : m + 8;
                int nn = n + (v & 1);
                float h = tanhf(acc[mf][nf][v] + bt[nn]);
                float zv = g_z[(size_t)mm*DD + nn];
                float xv = X[(size_t)mm*DD + nn];
                float o = (1.f - zv)*xv + zv*h;
                out[(size_t)mm*DD + nn] = o;
                g_stateH[(size_t)mm*DD + nn] = __float2half_rn(o);
            }
        }
    }
}

// ---------------- launch ----------------
extern "C" void kernel_launch(void* const* d_in, const int* in_sizes, int n_in,
                              void* d_out, int out_size)
{
    const float* input = (const float*)d_in[0];
    const float* gin   = (const float*)d_in[1];
    const float* gout  = (const float*)d_in[2];
    const float* W_in  = (const float*)d_in[3];
    const float* b_in  = (const float*)d_in[4];
    const float* W_out = (const float*)d_in[5];
    const float* b_out = (const float*)d_in[6];
    const float* W_r   = (const float*)d_in[7];
    const float* b_r   = (const float*)d_in[8];
    const float* W_z   = (const float*)d_in[9];
    const float* b_z   = (const float*)d_in[10];
    const float* W_t   = (const float*)d_in[11];
    const float* b_t   = (const float*)d_in[12];

    cudaFuncSetAttribute(k_graph_h,  cudaFuncAttributeMaxDynamicSharedMemorySize, SM_GR);
    cudaFuncSetAttribute(k_gfull_h,  cudaFuncAttributeMaxDynamicSharedMemorySize, SM_GF);
    cudaFuncSetAttribute(k_rz_h,     cudaFuncAttributeMaxDynamicSharedMemorySize, SM_RZ);
    cudaFuncSetAttribute(k_update_h, cudaFuncAttributeMaxDynamicSharedMemorySize, SM_UP);

    k_prep<<<1920, 256>>>(W_in, W_out, b_in, b_out, W_r, W_z, b_r, b_z, W_t, input);
    k_cvtA<<<dim3((MM/8)*(KGR/256), 2), 256>>>(gin, gout);

    int xsel = 2;                       // fp32 state: 2 => external (batchinput)
    for (int s = 0; s < NSTEPS; s++) {
        int osel = (s == NSTEPS-1) ? 2 : (s & 1);
        k_gfull_h <<<dim3(4, 64, 2), 256, SM_GF>>>(0);
        k_graph_h <<<dim3(8, 16, 2), 256, SM_GR>>>(0);
        k_rz_h    <<<dim3(2, 128), 256, SM_RZ>>>(input, xsel);
        k_update_h<<<256, 256, SM_UP>>>(input, xsel, b_t, (float*)d_out, osel);
        xsel = osel;
    }
}

// round 16
// speedup vs baseline: 1.5588x; 1.5588x over previous
#include <cuda_runtime.h>
#include <cuda_fp16.h>
#include <math.h>
#include <stdint.h>

#define BV 8
#define SLEN 1024
#define DD 128
#define EE 4
#define ED 512
#define MM (BV*SLEN)          // 8192 rows
#define KGR (SLEN*EE)         // 4096 graph K
#define NSTEPS 5
#define KB2 64                // K elems per pipeline stage (128B rows)

typedef __half fp16;

// smem per stage: (MTILE + NB) rows x 144 B
#define SM_GR (3*(128+128)*144)   // graph: M128/N128, 3 stages = 110592
#define SM_GF (2*(128+128)*144)   // gfull: M128/N128, 2 stages = 73728
#define SM_GT (2*(32+256)*144)    // gate phase1: M32/N256, 2 stages = 82944
// gate phase2 uses (32+128)*144*2 = 46080 of the same allocation; z parks above it

// ---------------- device scratch (no allocation allowed) ----------------
__device__ fp16 g_WeffH[2][ED*DD];        // folded W_in/W_out, ROW-PERMUTED n'=d*4+e
__device__ float g_biasP[2][ED];          // permuted b_in/b_out
__device__ fp16 g_WrzH[256*384];          // stacked [W_r; W_z] fp16
__device__ fp16 g_WtH[128*384];           // W_t fp16
__device__ float g_brz[256];
__device__ fp16 g_gh[(size_t)2*MM*KGR];       // fp16 gin/gout (134MB)
__device__ fp16 g_gfullT[(size_t)2*BV*DD*KGR];// [t][b][d=128][k=4096] fp16 K-major
__device__ fp16 g_gpartH[(size_t)2*2*MM*DD];  // split-K partials fp16 [ks][t][m][d]
__device__ fp16 g_gsumH[2][MM*DD];        // gi / go fp16 (GEMM A operand)
__device__ fp16 g_rgH[MM*DD];             // r * out, fp16
__device__ fp16 g_stateH[MM*DD];          // fp16 shadow of state
__device__ float g_stateA[MM*DD];
__device__ float g_stateB[MM*DD];

__device__ __forceinline__ const float* state_ptr(const float* ext, int sel) {
    return sel == 0 ? g_stateA : (sel == 1 ? g_stateB : ext);
}

__device__ __forceinline__ void mma_f16(float* d, const uint32_t* a, const uint32_t* b) {
    asm volatile(
        "mma.sync.aligned.m16n8k16.row.col.f32.f16.f16.f32 "
        "{%0,%1,%2,%3}, {%4,%5,%6,%7}, {%8,%9}, {%0,%1,%2,%3};"
        : "+f"(d[0]), "+f"(d[1]), "+f"(d[2]), "+f"(d[3])
        : "r"(a[0]), "r"(a[1]), "r"(a[2]), "r"(a[3]), "r"(b[0]), "r"(b[1]));
}
__device__ __forceinline__ void ldm_x4(uint32_t* r, uint32_t addr) {
    asm volatile("ldmatrix.sync.aligned.m8n8.x4.shared.b16 {%0,%1,%2,%3}, [%4];"
                 : "=r"(r[0]), "=r"(r[1]), "=r"(r[2]), "=r"(r[3]) : "r"(addr));
}
__device__ __forceinline__ void cp16(uint32_t smem_dst, const void* gsrc) {
    asm volatile("cp.async.cg.shared.global [%0], [%1], 16;" :: "r"(smem_dst), "l"(gsrc));
}
__device__ __forceinline__ void st32cg(void* p, uint32_t v) {
    asm volatile("st.global.cg.u32 [%0], %1;" :: "l"(p), "r"(v));
}
#define CP_COMMIT() asm volatile("cp.async.commit_group;" ::: "memory")

// ---------------- unified fp16 GEMM core ----------------
template<int KTOT, int LDA, int LDB, int NSTG, int MTILE, int NB, int NFRAG, int MF>
__device__ __forceinline__ void h_core(
    const fp16* __restrict__ A0, const fp16* __restrict__ A1, const fp16* __restrict__ A2,
    const fp16* __restrict__ Bt, int m0, int n0, float (&acc)[MF][NFRAG][4], char* dsm)
{
    constexpr int ATILE_B = MTILE*144;
    constexpr int STGB = ATILE_B + NB*144;
    constexpr int NITL = KTOT / KB2;
    constexpr int WMc = (MTILE == 128) ? 2 : 1;
    static_assert(MF == MTILE/(WMc*16), "MF mismatch");
    const uint32_t sb = (uint32_t)__cvta_generic_to_shared(dsm);
    const int tid = threadIdx.x, lane = tid & 31, wid = tid >> 5;
    const int l8 = lane & 7, q = lane >> 3;
    const int wm = (WMc == 2) ? (wid & 1) : 0;
    const int wn = (WMc == 2) ? (wid >> 1) : wid;

    auto issue = [&](int stg, int k0) {
        if (k0 < KTOT) {
            const fp16* Aseg; int kl;
            if (KTOT > LDA) {              // 3 x 128-wide segments
                Aseg = (k0 < 128) ? A0 : (k0 < 256 ? A1 : A2);
                kl = k0 & 127;
            } else { Aseg = A0; kl = k0; }
            uint32_t base = sb + stg*STGB;
            #pragma unroll
            for (int i = 0; i < MTILE*8/256; i++) {
                int c = tid + i*256, row = c >> 3, off = c & 7;
                cp16(base + row*144 + off*16,
                     Aseg + (size_t)(m0+row)*LDA + kl + off*8);
            }
            #pragma unroll
            for (int i = 0; i < NB*8/256; i++) {
                int c = tid + i*256, row = c >> 3, off = c & 7;
                cp16(base + ATILE_B + row*144 + off*16,
                     Bt + (size_t)(n0+row)*LDB + k0 + off*8);
            }
        }
        CP_COMMIT();
    };

    #pragma unroll
    for (int s = 0; s < NSTG-1; s++) issue(s, s*KB2);

    #pragma unroll 1
    for (int it = 0; it < NITL; ++it) {
        asm volatile("cp.async.wait_group %0;" :: "n"(NSTG-2) : "memory");
        __syncthreads();
        issue((it + NSTG-1) % NSTG, (it + NSTG-1)*KB2);

        const uint32_t sA = sb + (it % NSTG)*STGB;
        const uint32_t sB = sA + ATILE_B;
        #pragma unroll
        for (int kk = 0; kk < 4; kk++) {
            uint32_t afr[MF][4], bfr[NFRAG][2];
            #pragma unroll
            for (int mf = 0; mf < MF; mf++) {
                int row = wm*64 + mf*16 + (q & 1)*8 + l8;
                ldm_x4(afr[mf], sA + row*144 + kk*32 + (q >> 1)*16);
            }
            #pragma unroll
            for (int h = 0; h < NFRAG/2; h++) {
                uint32_t r[4];
                int row = wn*(8*NFRAG) + h*16 + (q >> 1)*8 + l8;
                ldm_x4(r, sB + row*144 + kk*32 + (q & 1)*16);
                bfr[2*h][0] = r[0]; bfr[2*h][1] = r[1];
                bfr[2*h+1][0] = r[2]; bfr[2*h+1][1] = r[3];
            }
            #pragma unroll
            for (int mf = 0; mf < MF; mf++)
                #pragma unroll
                for (int nf = 0; nf < NFRAG; nf++)
                    mma_f16(acc[mf][nf], afr[mf], bfr[nf]);
        }
    }
}

// ---------------- merged prep kernel (fold + stack + cvtX) ----------------
__global__ void k_prep(const float* __restrict__ Win, const float* __restrict__ Wout,
                       const float* __restrict__ b_in, const float* __restrict__ b_out,
                       const float* __restrict__ Wr, const float* __restrict__ Wz,
                       const float* __restrict__ br, const float* __restrict__ bz,
                       const float* __restrict__ Wt, const float* __restrict__ x)
{
    int b = blockIdx.x, tid = threadIdx.x;
    if (b < 512) {
        int idx = b*256 + tid;
        int t = idx >> 16, rem = idx & 65535, j = rem >> 7, d = rem & 127;
        const float* W = t ? Wout : Win;
        float s = 0.f;
        #pragma unroll
        for (int e = 0; e < EE; e++) s += W[(size_t)j*ED + e*DD + d];
        int np = (j & 127)*4 + (j >> 7);
        g_WeffH[t][np*DD + d] = __float2half_rn(s);
        if (d == 0) g_biasP[t][np] = (t ? b_out : b_in)[j];
    } else if (b < 896) {
        int i = (b - 512)*256 + tid;
        if (i < 256*384) {
            int row = i / 384, col = i % 384;
            g_WrzH[i] = __float2half_rn((row < 128) ? Wr[row*384 + col]
                                                    : Wz[(row-128)*384 + col]);
        }
        if (i < 128*384) g_WtH[i] = __float2half_rn(Wt[i]);
        if (i < 256) g_brz[i] = (i < 128) ? br[i] : bz[i-128];
    } else {
        size_t i = ((size_t)(b - 896)*256 + tid) * 4;
        float4 f = *(const float4*)(x + i);
        fp16 h[4];
        h[0]=__float2half_rn(f.x); h[1]=__float2half_rn(f.y);
        h[2]=__float2half_rn(f.z); h[3]=__float2half_rn(f.w);
        *(uint2*)(g_stateH + i) = *(uint2*)h;
    }
}

__global__ void k_cvtA(const float* __restrict__ gin, const float* __restrict__ gout) {
    int t = blockIdx.y;
    const float* src = t ? gout : gin;
    fp16* dst = g_gh + (size_t)t*MM*KGR;
    size_t i = ((size_t)blockIdx.x*blockDim.x + threadIdx.x) * 8;
    float4 f0 = *(const float4*)(src + i);
    float4 f1 = *(const float4*)(src + i + 4);
    fp16 h[8];
    h[0]=__float2half_rn(f0.x); h[1]=__float2half_rn(f0.y);
    h[2]=__float2half_rn(f0.z); h[3]=__float2half_rn(f0.w);
    h[4]=__float2half_rn(f1.x); h[5]=__float2half_rn(f1.y);
    h[6]=__float2half_rn(f1.z); h[7]=__float2half_rn(f1.w);
    *(uint4*)(dst + i) = *(uint4*)h;
}

// ---------------- K1: gfullT = (XH @ WeffH'^T + b') -> fp16 transposed, coalesced ----------------
__global__ __launch_bounds__(256) void k_gfull_h(int dummy)
{
    extern __shared__ char dsm[];
    const int t = blockIdx.z;
    const int m0 = blockIdx.y*128, n0 = blockIdx.x*128;
    float acc[4][4][4] = {};
    h_core<128,128,128,2,128,128,4,4>(g_stateH, g_stateH, g_stateH, g_WeffH[t], m0, n0, acc, dsm);

    const float* bias = g_biasP[t];
    const int lane = threadIdx.x & 31, wid = threadIdx.x >> 5;
    const int g = lane >> 2, tig = lane & 3;
    const int wm = wid & 1, wn = wid >> 1;
    const int bb = m0 >> 10;
    fp16* outT = g_gfullT + ((size_t)t*BV + bb)*DD*KGR;
    #pragma unroll
    for (int mf = 0; mf < 4; mf++) {
        int m = m0 + wm*64 + mf*16 + g;
        int s0 = m & (SLEN-1), s1 = (m+8) & (SLEN-1);
        #pragma unroll
        for (int nf = 0; nf < 4; nf++) {
            int np = n0 + wn*32 + nf*8 + 2*tig;        // n' = d*4+e, even
            int d = np >> 2, e = np & 3;
            fp16 p0[2] = {__float2half_rn(acc[mf][nf][0] + bias[np]),
                          __float2half_rn(acc[mf][nf][1] + bias[np+1])};
            fp16 p1[2] = {__float2half_rn(acc[mf][nf][2] + bias[np]),
                          __float2half_rn(acc[mf][nf][3] + bias[np+1])};
            *(uint32_t*)(outT + (size_t)d*KGR + s0*4 + e) = *(uint32_t*)p0;
            *(uint32_t*)(outT + (size_t)d*KGR + s1*4 + e) = *(uint32_t*)p1;
        }
    }
}

// ---------------- K2: graph GEMM, split-K(2), M128, 3 stages, fp16 partials ----------------
__global__ __launch_bounds__(256, 2) void k_graph_h(int dummy)
{
    extern __shared__ char dsm[];
    const int bt = blockIdx.y, t = bt & 1, b = bt >> 1;
    const int ks = blockIdx.z;
    const int m0 = blockIdx.x * 128;
    const fp16* A  = g_gh + (size_t)t*MM*KGR + (size_t)b*SLEN*KGR + ks*(KGR/2);
    const fp16* Bg = g_gfullT + ((size_t)t*BV + b)*DD*KGR + ks*(KGR/2);
    fp16* P = g_gpartH + (((size_t)ks*2 + t)*MM + (size_t)b*SLEN)*DD;

    float acc[4][4][4] = {};
    h_core<KGR/2, KGR, KGR, 3, 128, 128, 4, 4>(A, A, A, Bg, m0, 0, acc, dsm);

    const int lane = threadIdx.x & 31, wid = threadIdx.x >> 5;
    const int g = lane >> 2, tig = lane & 3;
    const int wm = wid & 1, wn = wid >> 1;
    #pragma unroll
    for (int mf = 0; mf < 4; mf++) {
        int m = m0 + wm*64 + mf*16 + g;
        #pragma unroll
        for (int nf = 0; nf < 4; nf++) {
            int n = wn*32 + nf*8 + 2*tig;
            fp16 p0[2] = {__float2half_rn(acc[mf][nf][0]), __float2half_rn(acc[mf][nf][1])};
            fp16 p1[2] = {__float2half_rn(acc[mf][nf][2]), __float2half_rn(acc[mf][nf][3])};
            *(uint32_t*)(P + (size_t)m*DD + n)     = *(uint32_t*)p0;
            *(uint32_t*)(P + (size_t)(m+8)*DD + n) = *(uint32_t*)p1;
        }
    }
}

// reduce fp16 split-K partials -> fp16 gsum (8 elems/thread)
__global__ void k_red() {
    size_t i = ((size_t)blockIdx.x*blockDim.x + threadIdx.x) * 8;  // over 2*MM*DD
    uint4 ua = *(const uint4*)(g_gpartH + i);
    uint4 ub = *(const uint4*)(g_gpartH + (size_t)2*MM*DD + i);
    const __half2* ha = (const __half2*)&ua;
    const __half2* hb = (const __half2*)&ub;
    __half2 o[4];
    #pragma unroll
    for (int j = 0; j < 4; j++) {
        float2 fa = __half22float2(ha[j]);
        float2 fb = __half22float2(hb[j]);
        o[j] = __floats2half2_rn(fa.x + fb.x, fa.y + fb.y);
    }
    *(uint4*)(&g_gsumH[0][0] + i) = *(uint4*)o;
}

// ---------------- K3: fused gate kernel, M32 tiles (256 CTAs) ----------------
// phase1: r,z = sigmoid([gi,go,X]@Wrz^T + b)  (N=256); rg -> global (cg), z -> smem park
// phase2: h = tanh([gi,go,rg]@Wt^T + bt); out = (1-z)*X + z*h
__global__ __launch_bounds__(256, 2) void k_gate_h(
    const float* __restrict__ Xext, int xsel,
    const float* __restrict__ bt,
    float* __restrict__ extOut, int osel)
{
    extern __shared__ char dsm[];
    const float* X = state_ptr(Xext, xsel);
    float* out = (osel == 0) ? g_stateA : (osel == 1 ? g_stateB : extOut);
    const int m0 = blockIdx.x*32;
    const int lane = threadIdx.x & 31, wid = threadIdx.x >> 5;
    const int g = lane >> 2, tig = lane & 3;
    float* zbuf = (float*)(dsm + 46080);   // [32][128], above phase2's pipeline region

    // ---- phase 1: N=256 over K=384 ----
    {
        float acc[2][4][4] = {};
        h_core<384,128,384,2,32,256,4,2>(g_gsumH[0], g_gsumH[1], g_stateH, g_WrzH, m0, 0, acc, dsm);
        #pragma unroll
        for (int mf = 0; mf < 2; mf++) {
            int m = m0 + mf*16 + g;
            #pragma unroll
            for (int nf = 0; nf < 4; nf++) {
                int n = wid*32 + nf*8 + 2*tig;   // 0..255, pair (n, n+1)
                #pragma unroll
                for (int half = 0; half < 2; half++) {   // rows m, m+8
                    int mm = m + half*8;
                    float v0 = acc[mf][nf][2*half+0] + g_brz[n];
                    float v1 = acc[mf][nf][2*half+1] + g_brz[n+1];
                    float s0 = 1.f/(1.f + expf(-v0));
                    float s1 = 1.f/(1.f + expf(-v1));
                    if (n < 128) {
                        fp16 p[2] = {__float2half_rn(s0 * X[(size_t)mm*DD + n]),
                                     __float2half_rn(s1 * X[(size_t)mm*DD + n+1])};
                        st32cg(g_rgH + (size_t)mm*DD + n, *(uint32_t*)p);
                    } else {
                        zbuf[(mm - m0)*128 + (n - 128)]     = s0;
                        zbuf[(mm - m0)*128 + (n - 128) + 1] = s1;
                    }
                }
            }
        }
    }
    __syncthreads();   // rg stores + zbuf visible block-wide; smem [0,46080) reusable

    // ---- phase 2: N=128 over K=384 (A seg2 = rg just written) ----
    {
        float acc[2][2][4] = {};
        h_core<384,128,384,2,32,128,2,2>(g_gsumH[0], g_gsumH[1], g_rgH, g_WtH, m0, 0, acc, dsm);
        #pragma unroll
        for (int mf = 0; mf < 2; mf++) {
            int m = m0 + mf*16 + g;
            #pragma unroll
            for (int nf = 0; nf < 2; nf++) {
                int n = wid*16 + nf*8 + 2*tig;
                #pragma unroll
                for (int v = 0; v < 4; v++) {
                    int mm = (v < 2) ? m : m + 8;
                    int nn = n + (v & 1);
                    float h = tanhf(acc[mf][nf][v] + bt[nn]);
                    float zv = zbuf[(mm - m0)*128 + nn];
                    float xv = X[(size_t)mm*DD + nn];
                    float o = (1.f - zv)*xv + zv*h;
                    out[(size_t)mm*DD + nn] = o;
                    g_stateH[(size_t)mm*DD + nn] = __float2half_rn(o);
                }
            }
        }
    }
}

// ---------------- launch ----------------
extern "C" void kernel_launch(void* const* d_in, const int* in_sizes, int n_in,
                              void* d_out, int out_size)
{
    const float* input = (const float*)d_in[0];
    const float* gin   = (const float*)d_in[1];
    const float* gout  = (const float*)d_in[2];
    const float* W_in  = (const float*)d_in[3];
    const float* b_in  = (const float*)d_in[4];
    const float* W_out = (const float*)d_in[5];
    const float* b_out = (const float*)d_in[6];
    const float* W_r   = (const float*)d_in[7];
    const float* b_r   = (const float*)d_in[8];
    const float* W_z   = (const float*)d_in[9];
    const float* b_z   = (const float*)d_in[10];
    const float* W_t   = (const float*)d_in[11];
    const float* b_t   = (const float*)d_in[12];

    cudaFuncSetAttribute(k_graph_h, cudaFuncAttributeMaxDynamicSharedMemorySize, SM_GR);
    cudaFuncSetAttribute(k_gfull_h, cudaFuncAttributeMaxDynamicSharedMemorySize, SM_GF);
    cudaFuncSetAttribute(k_gate_h,  cudaFuncAttributeMaxDynamicSharedMemorySize, SM_GT);

    k_prep<<<1920, 256>>>(W_in, W_out, b_in, b_out, W_r, W_z, b_r, b_z, W_t, input);
    k_cvtA<<<dim3((MM/8)*(KGR/256), 2), 256>>>(gin, gout);

    int xsel = 2;                       // fp32 state: 2 => external (batchinput)
    for (int s = 0; s < NSTEPS; s++) {
        int osel = (s == NSTEPS-1) ? 2 : (s & 1);
        k_gfull_h<<<dim3(4, 64, 2), 256, SM_GF>>>(0);
        k_graph_h<<<dim3(8, 16, 2), 256, SM_GR>>>(0);
        k_red    <<<(2*MM*DD/8)/256, 256>>>();
        k_gate_h <<<256, 256, SM_GT>>>(input, xsel, b_t, (float*)d_out, osel);
        xsel = osel;
    }
}